// round 4
// baseline (speedup 1.0000x reference)
#include <cuda_runtime.h>
#include <math.h>

// Problem constants (fixed shapes)
#define S_LEN 2048
#define B_SZ  64
#define H_DIM 1024
#define D_HALF 64
#define W_WIN 129            // 2*D+1
#define DCH   128            // d-chunk for GEMM partial
#define NDC   (H_DIM / DCH)  // 8

// Scratch (allocation-free)
__device__ float g_dotp[NDC * B_SZ * H_DIM];   // [dc][b][h]  2 MB
__device__ float g_p[B_SZ];
__device__ int   g_center[B_SZ];
__device__ float g_scores[B_SZ * W_WIN];
__device__ float g_attn[B_SZ * W_WIN];

// ---------------------------------------------------------------------------
// K1: partial GEMM  dotp[dc][b][h] = sum_{d in chunk dc} hidden[b][d]*Wp_w[h][d]
// grid: (16 h-tiles, 8 d-chunks) = 128 blocks (one wave), 256 threads.
// fp32 on purpose: p feeds round() -> window center; precision is structural.
// ---------------------------------------------------------------------------
__global__ __launch_bounds__(256, 1)
void k_gemm_partial(const float* __restrict__ hidden,
                    const float* __restrict__ Wp_w) {
    const int h0 = blockIdx.x * 64;
    const int dc = blockIdx.y;
    const int d0 = dc * DCH;

    __shared__ float sh_h[64][DCH + 1];   // [b][d] padded
    __shared__ float sh_w[DCH][65];       // [d][h] padded (transposed)

    const int tid  = threadIdx.x;
    const int lane = tid & 31;
    const int warp = tid >> 5;

    for (int idx = tid; idx < 64 * 32; idx += 256) {
        int b  = idx >> 5;
        int dq = (idx & 31) << 2;
        float4 v = *reinterpret_cast<const float4*>(&hidden[b * H_DIM + d0 + dq]);
        sh_h[b][dq + 0] = v.x; sh_h[b][dq + 1] = v.y;
        sh_h[b][dq + 2] = v.z; sh_h[b][dq + 3] = v.w;
    }
    for (int idx = tid; idx < 64 * 32; idx += 256) {
        int h  = idx >> 5;
        int dq = (idx & 31) << 2;
        float4 v = *reinterpret_cast<const float4*>(&Wp_w[(size_t)(h0 + h) * H_DIM + d0 + dq]);
        sh_w[dq + 0][h] = v.x; sh_w[dq + 1][h] = v.y;
        sh_w[dq + 2][h] = v.z; sh_w[dq + 3][h] = v.w;
    }
    __syncthreads();

    const int hl = lane & 15;
    const int bl = ((lane >> 4) << 2) + (warp << 3);

    float acc[4][4] = {};
#pragma unroll 16
    for (int d = 0; d < DCH; ++d) {
        float wv0 = sh_w[d][hl];
        float wv1 = sh_w[d][hl + 16];
        float wv2 = sh_w[d][hl + 32];
        float wv3 = sh_w[d][hl + 48];
        float hv0 = sh_h[bl + 0][d];
        float hv1 = sh_h[bl + 1][d];
        float hv2 = sh_h[bl + 2][d];
        float hv3 = sh_h[bl + 3][d];
        acc[0][0] += hv0 * wv0; acc[0][1] += hv0 * wv1; acc[0][2] += hv0 * wv2; acc[0][3] += hv0 * wv3;
        acc[1][0] += hv1 * wv0; acc[1][1] += hv1 * wv1; acc[1][2] += hv1 * wv2; acc[1][3] += hv1 * wv3;
        acc[2][0] += hv2 * wv0; acc[2][1] += hv2 * wv1; acc[2][2] += hv2 * wv2; acc[2][3] += hv2 * wv3;
        acc[3][0] += hv3 * wv0; acc[3][1] += hv3 * wv1; acc[3][2] += hv3 * wv2; acc[3][3] += hv3 * wv3;
    }

    float* outp = &g_dotp[(size_t)dc * (B_SZ * H_DIM)];
#pragma unroll
    for (int j = 0; j < 4; ++j) {
        int b = bl + j;
#pragma unroll
        for (int i = 0; i < 4; ++i) {
            int h = h0 + hl + 16 * i;
            outp[b * H_DIM + h] = acc[j][i];
        }
    }
}

// ---------------------------------------------------------------------------
// K2: per-b reduce -> p[b], center[b].  L2-resident inputs, ~0.5us.
// ---------------------------------------------------------------------------
__global__ __launch_bounds__(256)
void k_reduce_p(const float* __restrict__ Wp_b,
                const float* __restrict__ vp_w,
                const float* __restrict__ vp_b) {
    const int b = blockIdx.x;
    const int tid = threadIdx.x;
    float local = 0.f;
    for (int h = tid; h < H_DIM; h += 256) {
        float pa[NDC];
#pragma unroll
        for (int dc = 0; dc < NDC; ++dc)
            pa[dc] = g_dotp[dc * (B_SZ * H_DIM) + b * H_DIM + h];
        float s = Wp_b[h];
#pragma unroll
        for (int dc = 0; dc < NDC; ++dc) s += pa[dc];
        local += vp_w[h] * tanhf(s);
    }
    __shared__ float red[256];
    red[tid] = local;
    __syncthreads();
    for (int s = 128; s > 0; s >>= 1) {
        if (tid < s) red[tid] += red[tid + s];
        __syncthreads();
    }
    if (tid == 0) {
        float tot = red[0] + vp_b[0];
        float p = (float)S_LEN / (1.f + expf(-tot));
        g_p[b] = p;
        g_center[b] = (int)rintf(p);   // round-half-even == jnp.round
    }
}

// ---------------------------------------------------------------------------
// K3: scores, one warp per (b,w), full-chip grid, MLP=16.
// grid (33, 64), 128 threads. Out-of-range s -> exact 0 (zero-padded rows).
// ---------------------------------------------------------------------------
__global__ __launch_bounds__(128)
void k_scores(const float* __restrict__ hidden,
              const float* __restrict__ enc) {
    const int b    = blockIdx.y;
    const int w    = blockIdx.x * 4 + (threadIdx.x >> 5);
    const int lane = threadIdx.x & 31;
    if (w >= W_WIN) return;

    const int s = g_center[b] + w - D_HALF;
    float score = 0.f;
    if (s >= 0 && s < S_LEN) {
        const float4* e4 = reinterpret_cast<const float4*>(
            enc + ((size_t)s * B_SZ + b) * H_DIM);
        const float4* h4 = reinterpret_cast<const float4*>(
            hidden + (size_t)b * H_DIM);
        float4 e[8], hh[8];
#pragma unroll
        for (int k = 0; k < 8; ++k) e[k]  = e4[k * 32 + lane];   // batched LDG.128
#pragma unroll
        for (int k = 0; k < 8; ++k) hh[k] = h4[k * 32 + lane];
        float a0 = 0.f, a1 = 0.f, a2 = 0.f, a3 = 0.f;
#pragma unroll
        for (int k = 0; k < 8; ++k) {
            a0 += e[k].x * hh[k].x; a1 += e[k].y * hh[k].y;
            a2 += e[k].z * hh[k].z; a3 += e[k].w * hh[k].w;
        }
        float v = (a0 + a1) + (a2 + a3);
#pragma unroll
        for (int off = 16; off > 0; off >>= 1)
            v += __shfl_down_sync(0xffffffffu, v, off);
        score = v;
    }
    if (lane == 0) g_scores[b * W_WIN + w] = score;
}

// ---------------------------------------------------------------------------
// K4: softmax x gaussian -> d_out attn region + g_attn; zeroes context region.
// ---------------------------------------------------------------------------
__global__ __launch_bounds__(256)
void k_softmax(float* __restrict__ d_out) {
    const int b = blockIdx.x;
    const int tid = threadIdx.x;
    __shared__ float red[256];

    // zero context region (K5 accumulates with atomics)
    for (int i = tid; i < H_DIM; i += 256)
        d_out[B_SZ * W_WIN + b * H_DIM + i] = 0.f;

    float sc = (tid < W_WIN) ? g_scores[b * W_WIN + tid] : -1e30f;
    red[tid] = sc;
    __syncthreads();
    for (int s = 128; s > 0; s >>= 1) {
        if (tid < s) red[tid] = fmaxf(red[tid], red[tid + s]);
        __syncthreads();
    }
    float mx = red[0];
    __syncthreads();
    float e = (tid < W_WIN) ? expf(sc - mx) : 0.f;
    red[tid] = e;
    __syncthreads();
    for (int s = 128; s > 0; s >>= 1) {
        if (tid < s) red[tid] += red[tid + s];
        __syncthreads();
    }
    float denom = red[0];

    if (tid < W_WIN) {
        float p    = g_p[b];
        float pos  = (float)(g_center[b] + tid - D_HALF);
        float diff = pos - p;
        float val = (e / denom) * expf(-diff * diff * (1.f / 2048.f)); // stddev=D/2=32
        d_out[b * W_WIN + tid] = val;
        g_attn[b * W_WIN + tid] = val;
    }
}

// ---------------------------------------------------------------------------
// K5: context, grid (4 w-segments, 64 b), 256 threads, MLP=8, atomic combine.
// Window is L2-hot after K3.
// ---------------------------------------------------------------------------
__global__ __launch_bounds__(256)
void k_context(const float* __restrict__ enc,
               float* __restrict__ d_out) {
    const int seg = blockIdx.x;
    const int b   = blockIdx.y;
    const int tid = threadIdx.x;

    __shared__ float s_a[W_WIN];
    __shared__ int s_c2;
    if (tid == 0) s_c2 = g_center[b];
    for (int i = tid; i < W_WIN; i += 256) s_a[i] = g_attn[b * W_WIN + i];
    __syncthreads();
    const int c = s_c2;

    int lo = max(max(0, D_HALF - c), seg * 33);
    int hi = min(min(W_WIN, S_LEN + D_HALF - c), seg * 33 + 33);
    if (lo >= hi) return;

    const float4* base = reinterpret_cast<const float4*>(enc + (size_t)b * H_DIM) + tid;
    const size_t rs4 = (size_t)(B_SZ * H_DIM) / 4;

    float4 acc = make_float4(0.f, 0.f, 0.f, 0.f);
    int w = lo;
    for (; w + 7 < hi; w += 8) {
        float4 ev[8];
        float  av[8];
#pragma unroll
        for (int j = 0; j < 8; ++j) {
            ev[j] = base[(size_t)(c + w + j - D_HALF) * rs4];   // batched LDG.128
            av[j] = s_a[w + j];
        }
#pragma unroll
        for (int j = 0; j < 8; ++j) {
            acc.x += av[j] * ev[j].x; acc.y += av[j] * ev[j].y;
            acc.z += av[j] * ev[j].z; acc.w += av[j] * ev[j].w;
        }
    }
    for (; w < hi; ++w) {
        float4 ev = base[(size_t)(c + w - D_HALF) * rs4];
        float  a  = s_a[w];
        acc.x += a * ev.x; acc.y += a * ev.y;
        acc.z += a * ev.z; acc.w += a * ev.w;
    }

    float* o = d_out + B_SZ * W_WIN + b * H_DIM + tid * 4;
    atomicAdd(o + 0, acc.x);
    atomicAdd(o + 1, acc.y);
    atomicAdd(o + 2, acc.z);
    atomicAdd(o + 3, acc.w);
}

// ---------------------------------------------------------------------------
extern "C" void kernel_launch(void* const* d_in, const int* in_sizes, int n_in,
                              void* d_out, int out_size) {
    // metadata order: t, hidden, encoder_outputs, Wp_w, Wp_b, vp_w, vp_b
    const float* hidden = (const float*)d_in[1];
    const float* enc    = (const float*)d_in[2];
    const float* Wp_w   = (const float*)d_in[3];
    const float* Wp_b   = (const float*)d_in[4];
    const float* vp_w   = (const float*)d_in[5];
    const float* vp_b   = (const float*)d_in[6];
    float* out = (float*)d_out;

    k_gemm_partial<<<dim3(16, 8), 256>>>(hidden, Wp_w);
    k_reduce_p<<<64, 256>>>(Wp_b, vp_w, vp_b);
    k_scores<<<dim3(33, 64), 128>>>(hidden, enc);
    k_softmax<<<64, 256>>>(out);
    k_context<<<dim3(4, 64), 256>>>(enc, out);
}